// round 13
// baseline (speedup 1.0000x reference)
#include <cuda_runtime.h>
#include <cstdint>

// Problem constants: B=16, MAX_LEN=1024, DV=256, H=8, DH=32
#define NB 16
#define DVC 256
#define MAXN 12160

// Device scratch (allocation-free requirement)
__device__ float    g_qp  [MAXN * DVC];
__device__ uint16_t g_kp16[MAXN * DVC];   // bf16 projected K
__device__ uint16_t g_vp16[MAXN * DVC];   // bf16 projected V
__device__ float    g_att [MAXN * DVC];
__device__ int      g_starts[NB + 1];

// ---------------------------------------------------------------------------
// helpers
// ---------------------------------------------------------------------------
__device__ __forceinline__ float f2tf32f(float f) {
    uint32_t u;
    asm("cvt.rna.tf32.f32 %0, %1;" : "=r"(u) : "f"(f));
    return __uint_as_float(u);
}
__device__ __forceinline__ void mma_tf32(float c[4], const uint32_t a[4],
                                         uint32_t b0, uint32_t b1) {
    asm volatile(
        "mma.sync.aligned.m16n8k8.row.col.f32.tf32.tf32.f32 "
        "{%0,%1,%2,%3}, {%4,%5,%6,%7}, {%8,%9}, {%0,%1,%2,%3};"
        : "+f"(c[0]), "+f"(c[1]), "+f"(c[2]), "+f"(c[3])
        : "r"(a[0]), "r"(a[1]), "r"(a[2]), "r"(a[3]), "r"(b0), "r"(b1));
}
__device__ __forceinline__ void mma_bf16(float c[4], const uint32_t a[4],
                                         uint32_t b0, uint32_t b1) {
    asm volatile(
        "mma.sync.aligned.m16n8k16.row.col.f32.bf16.bf16.f32 "
        "{%0,%1,%2,%3}, {%4,%5,%6,%7}, {%8,%9}, {%0,%1,%2,%3};"
        : "+f"(c[0]), "+f"(c[1]), "+f"(c[2]), "+f"(c[3])
        : "r"(a[0]), "r"(a[1]), "r"(a[2]), "r"(a[3]), "r"(b0), "r"(b1));
}
__device__ __forceinline__ uint32_t bf16pk(float lo, float hi) {
    uint32_t r;
    asm("cvt.rn.bf16x2.f32 %0, %1, %2;" : "=r"(r) : "f"(hi), "f"(lo));
    return r;
}
__device__ __forceinline__ float ex2(float x) {
    float y; asm("ex2.approx.ftz.f32 %0, %1;" : "=f"(y) : "f"(x)); return y;
}
__device__ __forceinline__ void cp_async16(uint32_t smem_addr, const void* gptr, int src_bytes) {
    asm volatile("cp.async.cg.shared.global [%0], [%1], 16, %2;"
                 :: "r"(smem_addr), "l"(gptr), "r"(src_bytes));
}
__device__ __forceinline__ void cp_commit() {
    asm volatile("cp.async.commit_group;" ::: "memory");
}
__device__ __forceinline__ void ldsm_x4(uint32_t r[4], uint32_t addr) {
    asm volatile("ldmatrix.sync.aligned.m8n8.x4.shared.b16 {%0,%1,%2,%3}, [%4];"
                 : "=r"(r[0]), "=r"(r[1]), "=r"(r[2]), "=r"(r[3]) : "r"(addr));
}
__device__ __forceinline__ void ldsm_x4_t(uint32_t r[4], uint32_t addr) {
    asm volatile("ldmatrix.sync.aligned.m8n8.x4.trans.shared.b16 {%0,%1,%2,%3}, [%4];"
                 : "=r"(r[0]), "=r"(r[1]), "=r"(r[2]), "=r"(r[3]) : "r"(addr));
}

// ---------------------------------------------------------------------------
// Kernel 0: segment starts from sorted batch ids
// ---------------------------------------------------------------------------
__global__ void starts_kernel(const int* __restrict__ batch, int N) {
    int i = blockIdx.x * blockDim.x + threadIdx.x;
    if (i == 0) { g_starts[0] = 0; g_starts[NB] = N; }
    if (i > 0 && i < N && batch[i] != batch[i - 1]) g_starts[batch[i]] = i;
}

// ---------------------------------------------------------------------------
// tf32 GEMM body (proven staging, RNA rounding).
// MODE 0: f32 out.  MODE 1: Cf = A + relu(acc+bias).
// ---------------------------------------------------------------------------
template <int MODE>
__device__ __forceinline__ void gemm_body(
    const float* __restrict__ A, const float* __restrict__ W,
    const float* __restrict__ bias, float* __restrict__ Cf,
    int bm, int bn, int M,
    float (&As)[64][36], float (&Ws)[32][72])
{
    const int tid  = threadIdx.x;
    const int w    = tid >> 5;
    const int lane = tid & 31;
    const int g    = lane >> 2;
    const int m4   = lane & 3;
    const int wm   = (w >> 1) * 32;
    const int wn   = (w & 1) * 32;

    float acc[2][4][4];
#pragma unroll
    for (int mt = 0; mt < 2; mt++)
#pragma unroll
        for (int nt = 0; nt < 4; nt++)
#pragma unroll
            for (int j = 0; j < 4; j++) acc[mt][nt][j] = 0.f;

#pragma unroll 1
    for (int k0 = 0; k0 < 256; k0 += 32) {
#pragma unroll
        for (int i = 0; i < 4; i++) {
            int s = tid + i * 128;
            int r = s >> 3, c = (s & 7) * 4;
            float4 v = make_float4(0.f, 0.f, 0.f, 0.f);
            if (bm + r < M) v = *(const float4*)&A[(bm + r) * 256 + k0 + c];
            As[r][c + 0] = f2tf32f(v.x);
            As[r][c + 1] = f2tf32f(v.y);
            As[r][c + 2] = f2tf32f(v.z);
            As[r][c + 3] = f2tf32f(v.w);
        }
#pragma unroll
        for (int i = 0; i < 4; i++) {
            int s = tid + i * 128;
            int r = s >> 4, c = (s & 15) * 4;
            float4 v = *(const float4*)&W[(k0 + r) * 256 + bn + c];
            Ws[r][c + 0] = f2tf32f(v.x);
            Ws[r][c + 1] = f2tf32f(v.y);
            Ws[r][c + 2] = f2tf32f(v.z);
            Ws[r][c + 3] = f2tf32f(v.w);
        }
        __syncthreads();

#pragma unroll
        for (int k8 = 0; k8 < 4; k8++) {
            uint32_t a[2][4];
#pragma unroll
            for (int mt = 0; mt < 2; mt++) {
                int mr = wm + mt * 16;
                a[mt][0] = __float_as_uint(As[mr + g    ][k8 * 8 + m4]);
                a[mt][1] = __float_as_uint(As[mr + g + 8][k8 * 8 + m4]);
                a[mt][2] = __float_as_uint(As[mr + g    ][k8 * 8 + m4 + 4]);
                a[mt][3] = __float_as_uint(As[mr + g + 8][k8 * 8 + m4 + 4]);
            }
#pragma unroll
            for (int nt = 0; nt < 4; nt++) {
                uint32_t b0 = __float_as_uint(Ws[k8 * 8 + m4    ][wn + nt * 8 + g]);
                uint32_t b1 = __float_as_uint(Ws[k8 * 8 + m4 + 4][wn + nt * 8 + g]);
                mma_tf32(acc[0][nt], a[0], b0, b1);
                mma_tf32(acc[1][nt], a[1], b0, b1);
            }
        }
        __syncthreads();
    }

#pragma unroll
    for (int mt = 0; mt < 2; mt++) {
#pragma unroll
        for (int i = 0; i < 2; i++) {
            int row = bm + wm + mt * 16 + g + i * 8;
            if (row >= M) continue;
#pragma unroll
            for (int nt = 0; nt < 4; nt++) {
                int col = bn + wn + nt * 8 + 2 * m4;
                float x = acc[mt][nt][i * 2 + 0] + bias[col];
                float y = acc[mt][nt][i * 2 + 1] + bias[col + 1];
                if (MODE == 1) {
                    float2 av = *(const float2*)&A[row * 256 + col];
                    x = av.x + fmaxf(x, 0.f);
                    y = av.y + fmaxf(y, 0.f);
                }
                *(float2*)&Cf[row * 256 + col] = make_float2(x, y);
            }
        }
    }
}

// ---------------------------------------------------------------------------
// Fused K/V projection body: kp = A@Wk+bk, vp = A@Wv+bv share the A tile.
// A fragments loaded once per k8, used for BOTH weight matrices
// (24 LDS per 16 mma instead of 32; A global+smem traffic halved).
// bf16 outputs.
// ---------------------------------------------------------------------------
__device__ __forceinline__ void gemm_body_kv(
    const float* __restrict__ A,
    const float* __restrict__ Wk, const float* __restrict__ bk,
    const float* __restrict__ Wv, const float* __restrict__ bv,
    uint16_t* __restrict__ Ck, uint16_t* __restrict__ Cv,
    int bm, int bn, int M,
    float (&As)[64][36], float (&Ws)[2][32][72])
{
    const int tid  = threadIdx.x;
    const int w    = tid >> 5;
    const int lane = tid & 31;
    const int g    = lane >> 2;
    const int m4   = lane & 3;
    const int wm   = (w >> 1) * 32;
    const int wn   = (w & 1) * 32;

    float acc[2][2][4][4];   // [output kv][mt][nt][j]
#pragma unroll
    for (int o = 0; o < 2; o++)
#pragma unroll
        for (int mt = 0; mt < 2; mt++)
#pragma unroll
            for (int nt = 0; nt < 4; nt++)
#pragma unroll
                for (int j = 0; j < 4; j++) acc[o][mt][nt][j] = 0.f;

#pragma unroll 1
    for (int k0 = 0; k0 < 256; k0 += 32) {
#pragma unroll
        for (int i = 0; i < 4; i++) {
            int s = tid + i * 128;
            int r = s >> 3, c = (s & 7) * 4;
            float4 v = make_float4(0.f, 0.f, 0.f, 0.f);
            if (bm + r < M) v = *(const float4*)&A[(bm + r) * 256 + k0 + c];
            As[r][c + 0] = f2tf32f(v.x);
            As[r][c + 1] = f2tf32f(v.y);
            As[r][c + 2] = f2tf32f(v.z);
            As[r][c + 3] = f2tf32f(v.w);
        }
#pragma unroll
        for (int i = 0; i < 4; i++) {
            int s = tid + i * 128;
            int r = s >> 4, c = (s & 15) * 4;
            float4 vk = *(const float4*)&Wk[(k0 + r) * 256 + bn + c];
            Ws[0][r][c + 0] = f2tf32f(vk.x);
            Ws[0][r][c + 1] = f2tf32f(vk.y);
            Ws[0][r][c + 2] = f2tf32f(vk.z);
            Ws[0][r][c + 3] = f2tf32f(vk.w);
            float4 vv = *(const float4*)&Wv[(k0 + r) * 256 + bn + c];
            Ws[1][r][c + 0] = f2tf32f(vv.x);
            Ws[1][r][c + 1] = f2tf32f(vv.y);
            Ws[1][r][c + 2] = f2tf32f(vv.z);
            Ws[1][r][c + 3] = f2tf32f(vv.w);
        }
        __syncthreads();

#pragma unroll
        for (int k8 = 0; k8 < 4; k8++) {
            uint32_t a[2][4];
#pragma unroll
            for (int mt = 0; mt < 2; mt++) {
                int mr = wm + mt * 16;
                a[mt][0] = __float_as_uint(As[mr + g    ][k8 * 8 + m4]);
                a[mt][1] = __float_as_uint(As[mr + g + 8][k8 * 8 + m4]);
                a[mt][2] = __float_as_uint(As[mr + g    ][k8 * 8 + m4 + 4]);
                a[mt][3] = __float_as_uint(As[mr + g + 8][k8 * 8 + m4 + 4]);
            }
#pragma unroll
            for (int nt = 0; nt < 4; nt++) {
#pragma unroll
                for (int o = 0; o < 2; o++) {
                    uint32_t b0 = __float_as_uint(Ws[o][k8 * 8 + m4    ][wn + nt * 8 + g]);
                    uint32_t b1 = __float_as_uint(Ws[o][k8 * 8 + m4 + 4][wn + nt * 8 + g]);
                    mma_tf32(acc[o][0][nt], a[0], b0, b1);
                    mma_tf32(acc[o][1][nt], a[1], b0, b1);
                }
            }
        }
        __syncthreads();
    }

#pragma unroll
    for (int mt = 0; mt < 2; mt++) {
#pragma unroll
        for (int i = 0; i < 2; i++) {
            int row = bm + wm + mt * 16 + g + i * 8;
            if (row >= M) continue;
#pragma unroll
            for (int nt = 0; nt < 4; nt++) {
                int col = bn + wn + nt * 8 + 2 * m4;
                float xk = acc[0][mt][nt][i * 2 + 0] + bk[col];
                float yk = acc[0][mt][nt][i * 2 + 1] + bk[col + 1];
                *(uint32_t*)&Ck[row * 256 + col] = bf16pk(xk, yk);
                float xv = acc[1][mt][nt][i * 2 + 0] + bv[col];
                float yv = acc[1][mt][nt][i * 2 + 1] + bv[col + 1];
                *(uint32_t*)&Cv[row * 256 + col] = bf16pk(xv, yv);
            }
        }
    }
}

// ---------------------------------------------------------------------------
// Fused projections: grid = (ceil(N/64), 8).
// by 0..3: qp slabs (f32). by 4..7: fused kp/vp slabs (bf16).
// ---------------------------------------------------------------------------
__global__ __launch_bounds__(128) void proj_kernel(
    const float* __restrict__ q, const float* __restrict__ k,
    const float* __restrict__ Wq, const float* __restrict__ bq,
    const float* __restrict__ Wk, const float* __restrict__ bk,
    const float* __restrict__ Wv, const float* __restrict__ bv,
    int M)
{
    __shared__ float As[64][36];
    __shared__ float Ws[2][32][72];

    const int by = blockIdx.y;
    const int bn = (by & 3) * 64;
    const int bm = blockIdx.x * 64;

    if (by < 4)
        gemm_body<0>(q, Wq, bq, g_qp, bm, bn, M, As, Ws[0]);
    else
        gemm_body_kv(k, Wk, bk, Wv, bv, g_kp16, g_vp16, bm, bn, M, As, Ws);
}

// Output GEMM with fused residual + ReLU epilogue.
__global__ __launch_bounds__(128) void outgemm_kernel(
    const float* __restrict__ A, const float* __restrict__ W,
    const float* __restrict__ bias, float* __restrict__ C, int M)
{
    __shared__ float As[64][36];
    __shared__ float Ws[32][72];
    gemm_body<1>(A, W, bias, C, blockIdx.x * 64, blockIdx.y * 64, M, As, Ws);
}

// ---------------------------------------------------------------------------
// bf16 flash attention. Block = (128-q tile, batch, head), 8 warps x 16 q.
// Each K/V chunk now serves 128 queries (KV traffic halved vs ATQ=64).
// ---------------------------------------------------------------------------
#define ATQ 128
__global__ __launch_bounds__(256) void attn_kernel() {
    const int b = blockIdx.y;
    const int h = blockIdx.z;
    const int s0 = g_starts[b];
    const int L  = g_starts[b + 1] - s0;
    const int q0 = blockIdx.x * ATQ;
    if (q0 >= L) return;

    // [key 0..31][d 0..31 bf16 + 8 pad]; row stride 80B (conflict-free)
    __shared__ __align__(16) uint16_t Ks[2][32][40];
    __shared__ __align__(16) uint16_t Vs[2][32][40];

    const int tid  = threadIdx.x;
    const int w    = tid >> 5;
    const int lane = tid & 31;
    const int g    = lane >> 2;
    const int m4   = lane & 3;

    const int q0w = q0 + w * 16;
    const float qs = 0.17677669529663687f * 1.4426950408889634f;  // /sqrt(32)*log2e

    const uint32_t ksb = (uint32_t)__cvta_generic_to_shared(&Ks[0][0][0]);
    const uint32_t vsb = (uint32_t)__cvta_generic_to_shared(&Vs[0][0][0]);

    // 256 threads: one cp.async per thread covers K and V (128 segs each)
    auto issue_kv = [&](int ci, int buf) {
        int arr   = tid >> 7;             // 0: K, 1: V
        int row   = (tid & 127) >> 2;     // key 0..31
        int off16 = (tid & 3) * 16;
        int kg    = ci * 32 + row;
        int ok    = (kg < L) ? 16 : 0;
        int kr    = (kg < L) ? kg : 0;
        const uint16_t* gsrc = arr ? g_vp16 : g_kp16;
        const char* gp = (const char*)&gsrc[(s0 + kr) * 256 + h * 32] + off16;
        uint32_t dst = (arr ? vsb : ksb) + buf * 2560 + row * 80 + off16;
        cp_async16(dst, gp, ok);
    };

    // Q fragments: bf16x2, pre-scaled, register-resident
    uint32_t qa[2][4];
#pragma unroll
    for (int ks = 0; ks < 2; ks++) {
        int d0 = ks * 16 + 2 * m4;
        int r0 = q0w + g, r1 = q0w + g + 8;
        float2 z = make_float2(0.f, 0.f);
        float2 v00 = (r0 < L) ? *(const float2*)&g_qp[(s0 + r0) * 256 + h * 32 + d0]     : z;
        float2 v10 = (r1 < L) ? *(const float2*)&g_qp[(s0 + r1) * 256 + h * 32 + d0]     : z;
        float2 v01 = (r0 < L) ? *(const float2*)&g_qp[(s0 + r0) * 256 + h * 32 + d0 + 8] : z;
        float2 v11 = (r1 < L) ? *(const float2*)&g_qp[(s0 + r1) * 256 + h * 32 + d0 + 8] : z;
        qa[ks][0] = bf16pk(v00.x * qs, v00.y * qs);
        qa[ks][1] = bf16pk(v10.x * qs, v10.y * qs);
        qa[ks][2] = bf16pk(v01.x * qs, v01.y * qs);
        qa[ks][3] = bf16pk(v11.x * qs, v11.y * qs);
    }

    float o[4][4];
#pragma unroll
    for (int i = 0; i < 4; i++)
#pragma unroll
        for (int j = 0; j < 4; j++) o[i][j] = 0.f;
    float m0 = -1e30f, m1 = -1e30f, l0 = 0.f, l1 = 0.f;

    const int nc = (L + 31) >> 5;

    issue_kv(0, 0);
    cp_commit();

#pragma unroll 1
    for (int ci = 0; ci < nc; ci++) {
        const int buf = ci & 1;
        const int kc  = ci * 32;
        if (ci + 1 < nc) {
            issue_kv(ci + 1, buf ^ 1);
            cp_commit();
            asm volatile("cp.async.wait_group 1;" ::: "memory");
        } else {
            asm volatile("cp.async.wait_group 0;" ::: "memory");
        }
        __syncthreads();

        // K fragments: 4x ldmatrix.x4
        uint32_t kb[2][2][4];
        {
            int j = lane >> 3, r = lane & 7;
#pragma unroll
            for (int ks = 0; ks < 2; ks++)
#pragma unroll
                for (int np = 0; np < 2; np++) {
                    int key = np * 16 + ((j >> 1) << 3) + r;
                    int d   = ks * 16 + ((j & 1) << 3);
                    ldsm_x4(kb[ks][np], ksb + buf * 2560 + key * 80 + d * 2);
                }
        }

        // QK^T (8 mma)
        float sc[4][4];
#pragma unroll
        for (int nt = 0; nt < 4; nt++)
#pragma unroll
            for (int j = 0; j < 4; j++) sc[nt][j] = 0.f;
#pragma unroll
        for (int ks = 0; ks < 2; ks++)
#pragma unroll
            for (int nt = 0; nt < 4; nt++)
                mma_bf16(sc[nt], qa[ks],
                         kb[ks][nt >> 1][(nt & 1) * 2],
                         kb[ks][nt >> 1][(nt & 1) * 2 + 1]);

        // mask + online softmax (log2 domain)
        float mx0 = -1e30f, mx1 = -1e30f;
#pragma unroll
        for (int nt = 0; nt < 4; nt++) {
            int kcol0 = kc + nt * 8 + 2 * m4;
            if (kcol0 >= L)     { sc[nt][0] = -1e30f; sc[nt][2] = -1e30f; }
            if (kcol0 + 1 >= L) { sc[nt][1] = -1e30f; sc[nt][3] = -1e30f; }
            mx0 = fmaxf(mx0, fmaxf(sc[nt][0], sc[nt][1]));
            mx1 = fmaxf(mx1, fmaxf(sc[nt][2], sc[nt][3]));
        }
        mx0 = fmaxf(mx0, __shfl_xor_sync(0xffffffffu, mx0, 1));
        mx0 = fmaxf(mx0, __shfl_xor_sync(0xffffffffu, mx0, 2));
        mx1 = fmaxf(mx1, __shfl_xor_sync(0xffffffffu, mx1, 1));
        mx1 = fmaxf(mx1, __shfl_xor_sync(0xffffffffu, mx1, 2));

        float m0n = fmaxf(m0, mx0);
        float m1n = fmaxf(m1, mx1);
        float c0 = ex2(m0 - m0n);
        float c1 = ex2(m1 - m1n);
        m0 = m0n; m1 = m1n;

        float s0r = 0.f, s1r = 0.f;
#pragma unroll
        for (int nt = 0; nt < 4; nt++) {
            sc[nt][0] = ex2(sc[nt][0] - m0n);
            sc[nt][1] = ex2(sc[nt][1] - m0n);
            sc[nt][2] = ex2(sc[nt][2] - m1n);
            sc[nt][3] = ex2(sc[nt][3] - m1n);
            s0r += sc[nt][0] + sc[nt][1];
            s1r += sc[nt][2] + sc[nt][3];
        }
        s0r += __shfl_xor_sync(0xffffffffu, s0r, 1);
        s0r += __shfl_xor_sync(0xffffffffu, s0r, 2);
        s1r += __shfl_xor_sync(0xffffffffu, s1r, 1);
        s1r += __shfl_xor_sync(0xffffffffu, s1r, 2);
        l0 = l0 * c0 + s0r;
        l1 = l1 * c1 + s1r;

#pragma unroll
        for (int nt = 0; nt < 4; nt++) {
            o[nt][0] *= c0; o[nt][1] *= c0;
            o[nt][2] *= c1; o[nt][3] *= c1;
        }

        // P pack: QK C-fragment == PV A-fragment (k16 identity)
        uint32_t pa[2][4];
#pragma unroll
        for (int ks = 0; ks < 2; ks++) {
            pa[ks][0] = bf16pk(sc[2 * ks][0],     sc[2 * ks][1]);
            pa[ks][1] = bf16pk(sc[2 * ks][2],     sc[2 * ks][3]);
            pa[ks][2] = bf16pk(sc[2 * ks + 1][0], sc[2 * ks + 1][1]);
            pa[ks][3] = bf16pk(sc[2 * ks + 1][2], sc[2 * ks + 1][3]);
        }

        // V fragments: 4x ldmatrix.x4.trans
        uint32_t vb[2][2][4];
        {
            int j = lane >> 3, r = lane & 7;
#pragma unroll
            for (int ks = 0; ks < 2; ks++)
#pragma unroll
                for (int dp = 0; dp < 2; dp++) {
                    int key = ks * 16 + ((j & 1) << 3) + r;
                    int d   = dp * 16 + ((j >> 1) << 3);
                    ldsm_x4_t(vb[ks][dp], vsb + buf * 2560 + key * 80 + d * 2);
                }
        }

        // PV (8 mma)
#pragma unroll
        for (int ks = 0; ks < 2; ks++)
#pragma unroll
            for (int nt = 0; nt < 4; nt++)
                mma_bf16(o[nt], pa[ks],
                         vb[ks][nt >> 1][(nt & 1) * 2],
                         vb[ks][nt >> 1][(nt & 1) * 2 + 1]);

        __syncthreads();
    }

    // epilogue: normalize, residual +qp, store
    float il0 = 1.f / l0, il1 = 1.f / l1;
    int r0 = q0w + g, r1 = q0w + g + 8;
#pragma unroll
    for (int nt = 0; nt < 4; nt++) {
        int dh = nt * 8 + 2 * m4;
        if (r0 < L) {
            int base = (s0 + r0) * 256 + h * 32 + dh;
            float2 qv = *(const float2*)&g_qp[base];
            *(float2*)&g_att[base] =
                make_float2(o[nt][0] * il0 + qv.x, o[nt][1] * il0 + qv.y);
        }
        if (r1 < L) {
            int base = (s0 + r1) * 256 + h * 32 + dh;
            float2 qv = *(const float2*)&g_qp[base];
            *(float2*)&g_att[base] =
                make_float2(o[nt][2] * il1 + qv.x, o[nt][3] * il1 + qv.y);
        }
    }
}

// ---------------------------------------------------------------------------
// Launch
// ---------------------------------------------------------------------------
extern "C" void kernel_launch(void* const* d_in, const int* in_sizes, int n_in,
                              void* d_out, int out_size) {
    const float* q   = (const float*)d_in[0];
    const float* k   = (const float*)d_in[1];
    const int* batch_q = (const int*)d_in[2];
    const float* Wq = (const float*)d_in[4];
    const float* bq = (const float*)d_in[5];
    const float* Wk = (const float*)d_in[6];
    const float* bk = (const float*)d_in[7];
    const float* Wv = (const float*)d_in[8];
    const float* bv = (const float*)d_in[9];
    const float* Wo = (const float*)d_in[10];
    const float* bo = (const float*)d_in[11];
    float* out = (float*)d_out;

    const int N = in_sizes[0] / 256;

    float* att; cudaGetSymbolAddress((void**)&att, g_att);

    starts_kernel<<<(N + 255) / 256, 256>>>(batch_q, N);

    dim3 pgrid((N + 63) / 64, 8);
    proj_kernel<<<pgrid, 128>>>(q, k, Wq, bq, Wk, bk, Wv, bv, N);

    dim3 agrid(1024 / ATQ, NB, 8);
    attn_kernel<<<agrid, 256>>>();

    dim3 ogrid((N + 63) / 64, 4);
    outgemm_kernel<<<ogrid, 128>>>(att, Wo, bo, out, N);
}

// round 15
// speedup vs baseline: 1.0609x; 1.0609x over previous
#include <cuda_runtime.h>
#include <cstdint>

// Problem constants: B=16, MAX_LEN=1024, DV=256, H=8, DH=32
#define NB 16
#define DVC 256
#define MAXN 12160

// Device scratch (allocation-free requirement)
__device__ float    g_qp  [MAXN * DVC];
__device__ uint16_t g_kp16[MAXN * DVC];   // bf16 projected K
__device__ uint16_t g_vp16[MAXN * DVC];   // bf16 projected V
__device__ float    g_att [MAXN * DVC];
__device__ int      g_starts[NB + 1];

// ---------------------------------------------------------------------------
// helpers
// ---------------------------------------------------------------------------
__device__ __forceinline__ float f2tf32f(float f) {
    uint32_t u;
    asm("cvt.rna.tf32.f32 %0, %1;" : "=r"(u) : "f"(f));
    return __uint_as_float(u);
}
__device__ __forceinline__ void mma_tf32(float c[4], const uint32_t a[4],
                                         uint32_t b0, uint32_t b1) {
    asm volatile(
        "mma.sync.aligned.m16n8k8.row.col.f32.tf32.tf32.f32 "
        "{%0,%1,%2,%3}, {%4,%5,%6,%7}, {%8,%9}, {%0,%1,%2,%3};"
        : "+f"(c[0]), "+f"(c[1]), "+f"(c[2]), "+f"(c[3])
        : "r"(a[0]), "r"(a[1]), "r"(a[2]), "r"(a[3]), "r"(b0), "r"(b1));
}
__device__ __forceinline__ void mma_bf16(float c[4], const uint32_t a[4],
                                         uint32_t b0, uint32_t b1) {
    asm volatile(
        "mma.sync.aligned.m16n8k16.row.col.f32.bf16.bf16.f32 "
        "{%0,%1,%2,%3}, {%4,%5,%6,%7}, {%8,%9}, {%0,%1,%2,%3};"
        : "+f"(c[0]), "+f"(c[1]), "+f"(c[2]), "+f"(c[3])
        : "r"(a[0]), "r"(a[1]), "r"(a[2]), "r"(a[3]), "r"(b0), "r"(b1));
}
__device__ __forceinline__ uint32_t bf16pk(float lo, float hi) {
    uint32_t r;
    asm("cvt.rn.bf16x2.f32 %0, %1, %2;" : "=r"(r) : "f"(hi), "f"(lo));
    return r;
}
__device__ __forceinline__ float ex2(float x) {
    float y; asm("ex2.approx.ftz.f32 %0, %1;" : "=f"(y) : "f"(x)); return y;
}
__device__ __forceinline__ void cp_async16(uint32_t smem_addr, const void* gptr, int src_bytes) {
    asm volatile("cp.async.cg.shared.global [%0], [%1], 16, %2;"
                 :: "r"(smem_addr), "l"(gptr), "r"(src_bytes));
}
__device__ __forceinline__ void cp_commit() {
    asm volatile("cp.async.commit_group;" ::: "memory");
}
__device__ __forceinline__ void ldsm_x4(uint32_t r[4], uint32_t addr) {
    asm volatile("ldmatrix.sync.aligned.m8n8.x4.shared.b16 {%0,%1,%2,%3}, [%4];"
                 : "=r"(r[0]), "=r"(r[1]), "=r"(r[2]), "=r"(r[3]) : "r"(addr));
}
__device__ __forceinline__ void ldsm_x4_t(uint32_t r[4], uint32_t addr) {
    asm volatile("ldmatrix.sync.aligned.m8n8.x4.trans.shared.b16 {%0,%1,%2,%3}, [%4];"
                 : "=r"(r[0]), "=r"(r[1]), "=r"(r[2]), "=r"(r[3]) : "r"(addr));
}

// ---------------------------------------------------------------------------
// Kernel 0: segment starts from sorted batch ids
// ---------------------------------------------------------------------------
__global__ void starts_kernel(const int* __restrict__ batch, int N) {
    int i = blockIdx.x * blockDim.x + threadIdx.x;
    if (i == 0) { g_starts[0] = 0; g_starts[NB] = N; }
    if (i > 0 && i < N && batch[i] != batch[i - 1]) g_starts[batch[i]] = i;
}

// ---------------------------------------------------------------------------
// tf32 GEMM body (proven round-5/11 staging, RNA rounding).
// MODE 0: f32 out.  MODE 1: Cf = A + relu(acc+bias).  MODE 2: bf16 out (C16).
// ---------------------------------------------------------------------------
template <int MODE>
__device__ __forceinline__ void gemm_body(
    const float* __restrict__ A, const float* __restrict__ W,
    const float* __restrict__ bias, float* __restrict__ Cf,
    uint16_t* __restrict__ C16,
    int bm, int bn, int M,
    float (&As)[64][36], float (&Ws)[32][72])
{
    const int tid  = threadIdx.x;
    const int w    = tid >> 5;
    const int lane = tid & 31;
    const int g    = lane >> 2;
    const int m4   = lane & 3;
    const int wm   = (w >> 1) * 32;
    const int wn   = (w & 1) * 32;

    float acc[2][4][4];
#pragma unroll
    for (int mt = 0; mt < 2; mt++)
#pragma unroll
        for (int nt = 0; nt < 4; nt++)
#pragma unroll
            for (int j = 0; j < 4; j++) acc[mt][nt][j] = 0.f;

#pragma unroll 1
    for (int k0 = 0; k0 < 256; k0 += 32) {
#pragma unroll
        for (int i = 0; i < 4; i++) {
            int s = tid + i * 128;
            int r = s >> 3, c = (s & 7) * 4;
            float4 v = make_float4(0.f, 0.f, 0.f, 0.f);
            if (bm + r < M) v = *(const float4*)&A[(bm + r) * 256 + k0 + c];
            As[r][c + 0] = f2tf32f(v.x);
            As[r][c + 1] = f2tf32f(v.y);
            As[r][c + 2] = f2tf32f(v.z);
            As[r][c + 3] = f2tf32f(v.w);
        }
#pragma unroll
        for (int i = 0; i < 4; i++) {
            int s = tid + i * 128;
            int r = s >> 4, c = (s & 15) * 4;
            float4 v = *(const float4*)&W[(k0 + r) * 256 + bn + c];
            Ws[r][c + 0] = f2tf32f(v.x);
            Ws[r][c + 1] = f2tf32f(v.y);
            Ws[r][c + 2] = f2tf32f(v.z);
            Ws[r][c + 3] = f2tf32f(v.w);
        }
        __syncthreads();

#pragma unroll
        for (int k8 = 0; k8 < 4; k8++) {
            uint32_t a[2][4];
#pragma unroll
            for (int mt = 0; mt < 2; mt++) {
                int mr = wm + mt * 16;
                a[mt][0] = __float_as_uint(As[mr + g    ][k8 * 8 + m4]);
                a[mt][1] = __float_as_uint(As[mr + g + 8][k8 * 8 + m4]);
                a[mt][2] = __float_as_uint(As[mr + g    ][k8 * 8 + m4 + 4]);
                a[mt][3] = __float_as_uint(As[mr + g + 8][k8 * 8 + m4 + 4]);
            }
#pragma unroll
            for (int nt = 0; nt < 4; nt++) {
                uint32_t b0 = __float_as_uint(Ws[k8 * 8 + m4    ][wn + nt * 8 + g]);
                uint32_t b1 = __float_as_uint(Ws[k8 * 8 + m4 + 4][wn + nt * 8 + g]);
                mma_tf32(acc[0][nt], a[0], b0, b1);
                mma_tf32(acc[1][nt], a[1], b0, b1);
            }
        }
        __syncthreads();
    }

#pragma unroll
    for (int mt = 0; mt < 2; mt++) {
#pragma unroll
        for (int i = 0; i < 2; i++) {
            int row = bm + wm + mt * 16 + g + i * 8;
            if (row >= M) continue;
#pragma unroll
            for (int nt = 0; nt < 4; nt++) {
                int col = bn + wn + nt * 8 + 2 * m4;
                float x = acc[mt][nt][i * 2 + 0] + bias[col];
                float y = acc[mt][nt][i * 2 + 1] + bias[col + 1];
                if (MODE == 2) {
                    *(uint32_t*)&C16[row * 256 + col] = bf16pk(x, y);
                } else {
                    if (MODE == 1) {
                        float2 av = *(const float2*)&A[row * 256 + col];
                        x = av.x + fmaxf(x, 0.f);
                        y = av.y + fmaxf(y, 0.f);
                    }
                    *(float2*)&Cf[row * 256 + col] = make_float2(x, y);
                }
            }
        }
    }
}

// ---------------------------------------------------------------------------
// Fused projections (round-11 proven): qp (f32), kp16/vp16 (bf16).
// grid = (ceil(N/64), 12); blockIdx.y selects {matrix, 64-col slab}.
// ---------------------------------------------------------------------------
__global__ __launch_bounds__(128) void proj_kernel(
    const float* __restrict__ q, const float* __restrict__ k,
    const float* __restrict__ Wq, const float* __restrict__ bq,
    const float* __restrict__ Wk, const float* __restrict__ bk,
    const float* __restrict__ Wv, const float* __restrict__ bv,
    int M)
{
    __shared__ float As[64][36];
    __shared__ float Ws[32][72];

    const int by  = blockIdx.y;
    const int sel = by >> 2;
    const int bn  = (by & 3) * 64;
    const int bm  = blockIdx.x * 64;

    if (sel == 0)
        gemm_body<0>(q, Wq, bq, g_qp, nullptr, bm, bn, M, As, Ws);
    else if (sel == 1)
        gemm_body<2>(k, Wk, bk, nullptr, g_kp16, bm, bn, M, As, Ws);
    else
        gemm_body<2>(k, Wv, bv, nullptr, g_vp16, bm, bn, M, As, Ws);
}

// Output GEMM with fused residual + ReLU epilogue.
__global__ __launch_bounds__(128) void outgemm_kernel(
    const float* __restrict__ A, const float* __restrict__ W,
    const float* __restrict__ bias, float* __restrict__ C, int M)
{
    __shared__ float As[64][36];
    __shared__ float Ws[32][72];
    gemm_body<1>(A, W, bias, C, nullptr, blockIdx.x * 64, blockIdx.y * 64, M, As, Ws);
}

// ---------------------------------------------------------------------------
// bf16 flash attention, 64-key chunks (single change vs round 11).
// Block = (64-q tile, batch, head), 4 warps x 16 q. Per-chunk fixed costs
// (shuffle reductions, rescale, syncs) amortize over 64 keys instead of 32.
// ---------------------------------------------------------------------------
#define ATQ 64
#define KCH 64
__global__ __launch_bounds__(128) void attn_kernel() {
    const int b = blockIdx.y;
    const int h = blockIdx.z;
    const int s0 = g_starts[b];
    const int L  = g_starts[b + 1] - s0;
    const int q0 = blockIdx.x * ATQ;
    if (q0 >= L) return;

    // [key 0..63][d 0..31 bf16 + 8 pad]; row stride 80B; buf stride 5120B
    __shared__ __align__(16) uint16_t Ks[2][KCH][40];
    __shared__ __align__(16) uint16_t Vs[2][KCH][40];

    const int tid  = threadIdx.x;
    const int w    = tid >> 5;
    const int lane = tid & 31;
    const int g    = lane >> 2;
    const int m4   = lane & 3;

    const int q0w = q0 + w * 16;
    const float qs = 0.17677669529663687f * 1.4426950408889634f;  // /sqrt(32)*log2e

    const uint32_t ksb = (uint32_t)__cvta_generic_to_shared(&Ks[0][0][0]);
    const uint32_t vsb = (uint32_t)__cvta_generic_to_shared(&Vs[0][0][0]);

    // 512 cp.async segments (256 K + 256 V) over 128 threads = 4 each
    auto issue_kv = [&](int ci, int buf) {
#pragma unroll
        for (int s = 0; s < 4; s++) {
            int seg   = tid + s * 128;          // 0..511
            int arr   = seg >> 8;               // 0: K, 1: V
            int row   = (seg & 255) >> 2;       // key 0..63
            int off16 = (seg & 3) * 16;
            int kg    = ci * KCH + row;
            int ok    = (kg < L) ? 16 : 0;
            int kr    = (kg < L) ? kg : 0;
            const uint16_t* gsrc = arr ? g_vp16 : g_kp16;
            const char* gp = (const char*)&gsrc[(s0 + kr) * 256 + h * 32] + off16;
            uint32_t dst = (arr ? vsb : ksb) + buf * 5120 + row * 80 + off16;
            cp_async16(dst, gp, ok);
        }
    };

    // Q fragments: bf16x2, pre-scaled, register-resident
    uint32_t qa[2][4];
#pragma unroll
    for (int ks = 0; ks < 2; ks++) {
        int d0 = ks * 16 + 2 * m4;
        int r0 = q0w + g, r1 = q0w + g + 8;
        float2 z = make_float2(0.f, 0.f);
        float2 v00 = (r0 < L) ? *(const float2*)&g_qp[(s0 + r0) * 256 + h * 32 + d0]     : z;
        float2 v10 = (r1 < L) ? *(const float2*)&g_qp[(s0 + r1) * 256 + h * 32 + d0]     : z;
        float2 v01 = (r0 < L) ? *(const float2*)&g_qp[(s0 + r0) * 256 + h * 32 + d0 + 8] : z;
        float2 v11 = (r1 < L) ? *(const float2*)&g_qp[(s0 + r1) * 256 + h * 32 + d0 + 8] : z;
        qa[ks][0] = bf16pk(v00.x * qs, v00.y * qs);
        qa[ks][1] = bf16pk(v10.x * qs, v10.y * qs);
        qa[ks][2] = bf16pk(v01.x * qs, v01.y * qs);
        qa[ks][3] = bf16pk(v11.x * qs, v11.y * qs);
    }

    float o[4][4];
#pragma unroll
    for (int i = 0; i < 4; i++)
#pragma unroll
        for (int j = 0; j < 4; j++) o[i][j] = 0.f;
    float m0 = -1e30f, m1 = -1e30f, l0 = 0.f, l1 = 0.f;

    const int nc = (L + KCH - 1) / KCH;

    issue_kv(0, 0);
    cp_commit();

#pragma unroll 1
    for (int ci = 0; ci < nc; ci++) {
        const int buf = ci & 1;
        const int kc  = ci * KCH;
        if (ci + 1 < nc) {
            issue_kv(ci + 1, buf ^ 1);
            cp_commit();
            asm volatile("cp.async.wait_group 1;" ::: "memory");
        } else {
            asm volatile("cp.async.wait_group 0;" ::: "memory");
        }
        __syncthreads();

        // K fragments: 8x ldmatrix.x4 (covers 64 keys x 32 d)
        uint32_t kb[2][4][4];
        {
            int j = lane >> 3, r = lane & 7;
#pragma unroll
            for (int ks = 0; ks < 2; ks++)
#pragma unroll
                for (int np = 0; np < 4; np++) {
                    int key = np * 16 + ((j >> 1) << 3) + r;
                    int d   = ks * 16 + ((j & 1) << 3);
                    ldsm_x4(kb[ks][np], ksb + buf * 5120 + key * 80 + d * 2);
                }
        }

        // QK^T: S[16][64] per warp (16 mma)
        float sc[8][4];
#pragma unroll
        for (int nt = 0; nt < 8; nt++)
#pragma unroll
            for (int j = 0; j < 4; j++) sc[nt][j] = 0.f;
#pragma unroll
        for (int ks = 0; ks < 2; ks++)
#pragma unroll
            for (int nt = 0; nt < 8; nt++)
                mma_bf16(sc[nt], qa[ks],
                         kb[ks][nt >> 1][(nt & 1) * 2],
                         kb[ks][nt >> 1][(nt & 1) * 2 + 1]);

        // mask + online softmax (log2 domain)
        float mx0 = -1e30f, mx1 = -1e30f;
#pragma unroll
        for (int nt = 0; nt < 8; nt++) {
            int kcol0 = kc + nt * 8 + 2 * m4;
            if (kcol0 >= L)     { sc[nt][0] = -1e30f; sc[nt][2] = -1e30f; }
            if (kcol0 + 1 >= L) { sc[nt][1] = -1e30f; sc[nt][3] = -1e30f; }
            mx0 = fmaxf(mx0, fmaxf(sc[nt][0], sc[nt][1]));
            mx1 = fmaxf(mx1, fmaxf(sc[nt][2], sc[nt][3]));
        }
        mx0 = fmaxf(mx0, __shfl_xor_sync(0xffffffffu, mx0, 1));
        mx0 = fmaxf(mx0, __shfl_xor_sync(0xffffffffu, mx0, 2));
        mx1 = fmaxf(mx1, __shfl_xor_sync(0xffffffffu, mx1, 1));
        mx1 = fmaxf(mx1, __shfl_xor_sync(0xffffffffu, mx1, 2));

        float m0n = fmaxf(m0, mx0);
        float m1n = fmaxf(m1, mx1);
        float c0 = ex2(m0 - m0n);
        float c1 = ex2(m1 - m1n);
        m0 = m0n; m1 = m1n;

        float s0r = 0.f, s1r = 0.f;
#pragma unroll
        for (int nt = 0; nt < 8; nt++) {
            sc[nt][0] = ex2(sc[nt][0] - m0n);
            sc[nt][1] = ex2(sc[nt][1] - m0n);
            sc[nt][2] = ex2(sc[nt][2] - m1n);
            sc[nt][3] = ex2(sc[nt][3] - m1n);
            s0r += sc[nt][0] + sc[nt][1];
            s1r += sc[nt][2] + sc[nt][3];
        }
        s0r += __shfl_xor_sync(0xffffffffu, s0r, 1);
        s0r += __shfl_xor_sync(0xffffffffu, s0r, 2);
        s1r += __shfl_xor_sync(0xffffffffu, s1r, 1);
        s1r += __shfl_xor_sync(0xffffffffu, s1r, 2);
        l0 = l0 * c0 + s0r;
        l1 = l1 * c1 + s1r;

#pragma unroll
        for (int nt = 0; nt < 4; nt++) {
            o[nt][0] *= c0; o[nt][1] *= c0;
            o[nt][2] *= c1; o[nt][3] *= c1;
        }

        // P pack: QK C-fragment == PV A-fragment (k16 identity); K-dim = 64
        uint32_t pa[4][4];
#pragma unroll
        for (int kp = 0; kp < 4; kp++) {
            pa[kp][0] = bf16pk(sc[2 * kp][0],     sc[2 * kp][1]);
            pa[kp][1] = bf16pk(sc[2 * kp][2],     sc[2 * kp][3]);
            pa[kp][2] = bf16pk(sc[2 * kp + 1][0], sc[2 * kp + 1][1]);
            pa[kp][3] = bf16pk(sc[2 * kp + 1][2], sc[2 * kp + 1][3]);
        }

        // V fragments: 8x ldmatrix.x4.trans (64 keys x 32 d)
        uint32_t vb[4][2][4];
        {
            int j = lane >> 3, r = lane & 7;
#pragma unroll
            for (int kp = 0; kp < 4; kp++)
#pragma unroll
                for (int dp = 0; dp < 2; dp++) {
                    int key = kp * 16 + ((j & 1) << 3) + r;
                    int d   = dp * 16 + ((j >> 1) << 3);
                    ldsm_x4_t(vb[kp][dp], vsb + buf * 5120 + key * 80 + d * 2);
                }
        }

        // PV: O[16][32] += P[16][64] @ V[64][32] (16 mma)
#pragma unroll
        for (int kp = 0; kp < 4; kp++)
#pragma unroll
            for (int nt = 0; nt < 4; nt++)
                mma_bf16(o[nt], pa[kp],
                         vb[kp][nt >> 1][(nt & 1) * 2],
                         vb[kp][nt >> 1][(nt & 1) * 2 + 1]);

        __syncthreads();
    }

    // epilogue: normalize, residual +qp, store
    float il0 = 1.f / l0, il1 = 1.f / l1;
    int r0 = q0w + g, r1 = q0w + g + 8;
#pragma unroll
    for (int nt = 0; nt < 4; nt++) {
        int dh = nt * 8 + 2 * m4;
        if (r0 < L) {
            int base = (s0 + r0) * 256 + h * 32 + dh;
            float2 qv = *(const float2*)&g_qp[base];
            *(float2*)&g_att[base] =
                make_float2(o[nt][0] * il0 + qv.x, o[nt][1] * il0 + qv.y);
        }
        if (r1 < L) {
            int base = (s0 + r1) * 256 + h * 32 + dh;
            float2 qv = *(const float2*)&g_qp[base];
            *(float2*)&g_att[base] =
                make_float2(o[nt][2] * il1 + qv.x, o[nt][3] * il1 + qv.y);
        }
    }
}

// ---------------------------------------------------------------------------
// Launch
// ---------------------------------------------------------------------------
extern "C" void kernel_launch(void* const* d_in, const int* in_sizes, int n_in,
                              void* d_out, int out_size) {
    const float* q   = (const float*)d_in[0];
    const float* k   = (const float*)d_in[1];
    const int* batch_q = (const int*)d_in[2];
    const float* Wq = (const float*)d_in[4];
    const float* bq = (const float*)d_in[5];
    const float* Wk = (const float*)d_in[6];
    const float* bk = (const float*)d_in[7];
    const float* Wv = (const float*)d_in[8];
    const float* bv = (const float*)d_in[9];
    const float* Wo = (const float*)d_in[10];
    const float* bo = (const float*)d_in[11];
    float* out = (float*)d_out;

    const int N = in_sizes[0] / 256;

    float* att; cudaGetSymbolAddress((void**)&att, g_att);

    starts_kernel<<<(N + 255) / 256, 256>>>(batch_q, N);

    dim3 pgrid((N + 63) / 64, 12);
    proj_kernel<<<pgrid, 128>>>(q, k, Wq, bq, Wk, bk, Wv, bv, N);

    dim3 agrid(1024 / ATQ, NB, 8);
    attn_kernel<<<agrid, 128>>>();

    dim3 ogrid((N + 63) / 64, 4);
    outgemm_kernel<<<ogrid, 128>>>(att, Wo, bo, out, N);
}